// round 8
// baseline (speedup 1.0000x reference)
#include <cuda_runtime.h>
#include <cuda_fp16.h>
#include <cstdint>

#define DIN   4096
#define DOUT  4096
#define NTOK  8192
#define KPAD  4224   /* DIN + 128 lora cols */
#define NEXP  8

// ---------------- scratch (device globals; no allocation) ----------------
__device__ __align__(1024) __half g_Xg[(size_t)NTOK * KPAD];   // [token,k] 0:4096 = x f16, 4096: = g
__device__ __align__(1024) __half g_WB[(size_t)DOUT * KPAD];   // [o,k]     0:4096 = W,    4096: = Bflat
__device__ __align__(1024) __half g_Ah[(size_t)128 * DIN];     // [e*16+r, k]
__device__ __align__(256)  float  g_comb[(size_t)NTOK * NEXP]; // scaled combine weights

// ---------------- helpers ----------------
__device__ __forceinline__ uint32_t smem_u32(const void* p){
  uint32_t a; asm("{ .reg .u64 t; cvta.to.shared.u64 t, %1; cvt.u32.u64 %0, t; }" : "=r"(a) : "l"(p)); return a;
}
__device__ __forceinline__ uint32_t ph2(float a, float b){
  __half2 h = __floats2half2_rn(a, b);
  return *reinterpret_cast<uint32_t*>(&h);
}
__device__ __forceinline__ void cp16(uint32_t saddr, const void* g){
  asm volatile("cp.async.cg.shared.global [%0], [%1], 16;" :: "r"(saddr), "l"(g));
}
__device__ __forceinline__ void ldm_x4(uint32_t* d, uint32_t addr){
  asm volatile("ldmatrix.sync.aligned.m8n8.x4.shared.b16 {%0,%1,%2,%3}, [%4];"
    : "=r"(d[0]), "=r"(d[1]), "=r"(d[2]), "=r"(d[3]) : "r"(addr));
}
__device__ __forceinline__ void mma16816(float* c, const uint32_t* a, const uint32_t* b){
  asm volatile("mma.sync.aligned.m16n8k16.row.col.f32.f16.f16.f32 "
    "{%0,%1,%2,%3}, {%4,%5,%6,%7}, {%8,%9}, {%0,%1,%2,%3};"
    : "+f"(c[0]), "+f"(c[1]), "+f"(c[2]), "+f"(c[3])
    : "r"(a[0]), "r"(a[1]), "r"(a[2]), "r"(a[3]), "r"(b[0]), "r"(b[1]));
}

// ---------------- conversion kernels ----------------
__global__ void conv_pad_k(const float* __restrict__ src, __half* __restrict__ dst){
  int gid = blockIdx.x * 256 + threadIdx.x;
  int row = gid >> 9, cb = gid & 511;
  const float4* s = reinterpret_cast<const float4*>(src + ((size_t)row << 12)) + (cb << 1);
  float4 a = s[0], b = s[1];
  uint4 o; o.x = ph2(a.x,a.y); o.y = ph2(a.z,a.w); o.z = ph2(b.x,b.y); o.w = ph2(b.z,b.w);
  *(reinterpret_cast<uint4*>(dst + (size_t)row * KPAD) + cb) = o;
}
__global__ void conv_flat_k(const float* __restrict__ src){
  int gid = blockIdx.x * 256 + threadIdx.x;
  const float4* s = reinterpret_cast<const float4*>(src) + (gid << 1);
  float4 a = s[0], b = s[1];
  uint4 o; o.x = ph2(a.x,a.y); o.y = ph2(a.z,a.w); o.z = ph2(b.x,b.y); o.w = ph2(b.z,b.w);
  *(reinterpret_cast<uint4*>(g_Ah) + gid) = o;
}
__global__ void conv_bstack_k(const float* __restrict__ B){
  int gid = blockIdx.x * 256 + threadIdx.x;
  int e = gid >> 12, o = gid & 4095;
  const float4* s = reinterpret_cast<const float4*>(B + (((size_t)(e << 12) + o) << 4));
  float4 a = s[0], b = s[1], c = s[2], d = s[3];
  uint4 o0; o0.x = ph2(a.x,a.y); o0.y = ph2(a.z,a.w); o0.z = ph2(b.x,b.y); o0.w = ph2(b.z,b.w);
  uint4 o1; o1.x = ph2(c.x,c.y); o1.y = ph2(c.z,c.w); o1.z = ph2(d.x,d.y); o1.w = ph2(d.z,d.w);
  uint4* dp = reinterpret_cast<uint4*>(g_WB + (size_t)o * KPAD + DIN + e * 16);
  dp[0] = o0; dp[1] = o1;
}

// ---------------- router: exact fp32 top-2 softmax-renorm, SCALING folded ----------------
__global__ __launch_bounds__(256) void router_k(const float* __restrict__ x,
                                                const float* __restrict__ Wr){
  int t = blockIdx.x * 8 + (threadIdx.x >> 5);
  int lane = threadIdx.x & 31;
  const float4* xr = reinterpret_cast<const float4*>(x + ((size_t)t << 12));
  float acc[NEXP];
  #pragma unroll
  for (int e = 0; e < NEXP; ++e) acc[e] = 0.f;
  for (int i = 0; i < 32; ++i) {
    float4 xa = xr[lane + i * 32];
    #pragma unroll
    for (int e = 0; e < NEXP; ++e) {
      float4 w = reinterpret_cast<const float4*>(Wr + ((size_t)e << 12))[lane + i * 32];
      acc[e] += xa.x * w.x + xa.y * w.y + xa.z * w.z + xa.w * w.w;
    }
  }
  #pragma unroll
  for (int e = 0; e < NEXP; ++e)
    #pragma unroll
    for (int s = 16; s > 0; s >>= 1) acc[e] += __shfl_xor_sync(0xFFFFFFFFu, acc[e], s);
  if (lane == 0) {
    int i1 = 0; float m1 = acc[0];
    #pragma unroll
    for (int e = 1; e < NEXP; ++e) if (acc[e] > m1) { m1 = acc[e]; i1 = e; }
    int i2 = (i1 == 0) ? 1 : 0; float m2 = acc[i2];
    #pragma unroll
    for (int e = 0; e < NEXP; ++e) if (e != i1 && acc[e] > m2) { m2 = acc[e]; i2 = e; }
    float r  = expf(m2 - m1);
    float w1 = 1.f / (1.f + r);
    float w2 = r * w1;
    float o[NEXP];
    #pragma unroll
    for (int e = 0; e < NEXP; ++e) o[e] = 0.f;
    o[i1] = 2.0f * w1;  // SCALING = 32/16 = 2
    o[i2] = 2.0f * w2;
    #pragma unroll
    for (int e = 0; e < NEXP; ++e) g_comb[(size_t)t * NEXP + e] = o[e];
  }
}

// ---------------- mma.sync GEMM: C[M,N] = A[M,K] * B[N,K]^T ----------------
// 256 thr, 8 warps as 2(m) x 4(n); CTA tile 128 x BN; warp tile 64 x BN/4; BK=32; 4-stage cp.async.
// Smem rows padded to 80B (conflict-free ldmatrix, pitch = 20 banks).
// HEPI=false: out[m][n] = acc + bias[n] (fp32). HEPI=true: f16 pair into g_Xg[m][DIN+n] scaled by comb.
template<int BN, bool HEPI>
__global__ __launch_bounds__(256, 1)
void mma_gemm_k(const __half* __restrict__ Ag, int lda,
                const __half* __restrict__ Bg, int ldb, int nch,
                const float* __restrict__ bias, float* __restrict__ out){
  constexpr int NST = 4;
  constexpr int WN  = BN / 4;            // warp n-span
  constexpr int NT  = WN / 8;            // n-tiles (m16n8) per warp
  constexpr int SSTA = 128 * 80;         // A stage bytes (80B-padded rows)
  constexpr int SST  = SSTA + BN * 80;   // stage bytes
  extern __shared__ __align__(128) char smem[];
  const uint32_t sb = smem_u32(smem);

  const int tid = threadIdx.x, wid = tid >> 5, lane = tid & 31;
  const int wm = wid >> 2, wn = wid & 3;
  const int mBase = blockIdx.y * 128, nBase = blockIdx.x * BN;

  // per-thread ldmatrix base offsets (within a stage)
  const uint32_t aOff = (uint32_t)(wm * 64 + (lane & 15)) * 80 + ((lane >> 4) * 16);
  const uint32_t bOff = (uint32_t)(wn * WN + ((lane >> 4) & 1) * 8 + (lane & 7)) * 80
                        + (((lane >> 3) & 1) * 16);

  float acc[4][NT][4];
  #pragma unroll
  for (int mt = 0; mt < 4; ++mt)
    #pragma unroll
    for (int nt = 0; nt < NT; ++nt)
      #pragma unroll
      for (int q = 0; q < 4; ++q) acc[mt][nt][q] = 0.f;

  auto load_stage = [&](int kc, int st){
    uint32_t sA = sb + st * SST;
    uint32_t sB = sA + SSTA;
    #pragma unroll
    for (int i = 0; i < 2; ++i) {                 // A: 512 segs
      int s = tid + i * 256;
      int row = s >> 2, c = s & 3;
      cp16(sA + row * 80 + c * 16,
           Ag + (size_t)(mBase + row) * lda + kc * 32 + c * 8);
    }
    #pragma unroll
    for (int i = 0; i < BN / 64; ++i) {           // B: BN*4 segs
      int s = tid + i * 256;
      int row = s >> 2, c = s & 3;
      cp16(sB + row * 80 + c * 16,
           Bg + (size_t)(nBase + row) * ldb + kc * 32 + c * 8);
    }
    asm volatile("cp.async.commit_group;" ::: "memory");
  };

  #pragma unroll
  for (int s = 0; s < NST - 1; ++s) load_stage(s, s);

  #pragma unroll 1
  for (int kc = 0; kc < nch; ++kc) {
    asm volatile("cp.async.wait_group %0;" :: "n"(NST - 2) : "memory");
    __syncthreads();
    const int st = kc & (NST - 1);
    const uint32_t sA = sb + st * SST + aOff;
    const uint32_t sB = sb + st * SST + SSTA + bOff;

    #pragma unroll
    for (int kk = 0; kk < 2; ++kk) {
      uint32_t a[4][4];
      #pragma unroll
      for (int mt = 0; mt < 4; ++mt)
        ldm_x4(a[mt], sA + mt * (16 * 80) + kk * 32);
      uint32_t b[NT][2];
      #pragma unroll
      for (int bp = 0; bp < NT / 2; ++bp) {
        uint32_t d[4];
        ldm_x4(d, sB + bp * (16 * 80) + kk * 32);
        b[2*bp][0] = d[0]; b[2*bp][1] = d[1];
        b[2*bp+1][0] = d[2]; b[2*bp+1][1] = d[3];
      }
      #pragma unroll
      for (int mt = 0; mt < 4; ++mt)
        #pragma unroll
        for (int nt = 0; nt < NT; ++nt)
          mma16816(acc[mt][nt], a[mt], b[nt]);
    }
    __syncthreads();
    if (kc + NST - 1 < nch) load_stage(kc + NST - 1, (kc + NST - 1) & (NST - 1));
  }

  // epilogue
  const int m0 = mBase + wm * 64 + (lane >> 2);
  const int n0 = nBase + wn * WN + (lane & 3) * 2;
  #pragma unroll
  for (int mt = 0; mt < 4; ++mt) {
    const int r0 = m0 + mt * 16, r1 = r0 + 8;
    #pragma unroll
    for (int nt = 0; nt < NT; ++nt) {
      const int n = n0 + nt * 8;
      if (HEPI) {
        const int e = n >> 4;   // n, n+1 in same 16-col expert block (n even)
        float s0 = g_comb[(size_t)r0 * NEXP + e];
        float s1 = g_comb[(size_t)r1 * NEXP + e];
        *reinterpret_cast<uint32_t*>(g_Xg + (size_t)r0 * KPAD + DIN + n) =
            ph2(acc[mt][nt][0] * s0, acc[mt][nt][1] * s0);
        *reinterpret_cast<uint32_t*>(g_Xg + (size_t)r1 * KPAD + DIN + n) =
            ph2(acc[mt][nt][2] * s1, acc[mt][nt][3] * s1);
      } else {
        const float2 bv = *reinterpret_cast<const float2*>(bias + n);
        float2 v0; v0.x = acc[mt][nt][0] + bv.x; v0.y = acc[mt][nt][1] + bv.y;
        float2 v1; v1.x = acc[mt][nt][2] + bv.x; v1.y = acc[mt][nt][3] + bv.y;
        *reinterpret_cast<float2*>(out + (size_t)r0 * DOUT + n) = v0;
        *reinterpret_cast<float2*>(out + (size_t)r1 * DOUT + n) = v1;
      }
    }
  }
}

// ---------------- host ----------------
extern "C" void kernel_launch(void* const* d_in, const int* in_sizes, int n_in,
                              void* d_out, int out_size){
  (void)in_sizes; (void)n_in; (void)out_size;
  const float* x   = (const float*)d_in[0];
  const float* W   = (const float*)d_in[1];
  const float* b   = (const float*)d_in[2];
  const float* Wr  = (const float*)d_in[3];
  const float* A   = (const float*)d_in[4];
  const float* B   = (const float*)d_in[5];
  float* out = (float*)d_out;

  void *pXg = nullptr, *pWB = nullptr, *pAh = nullptr;
  cudaGetSymbolAddress(&pXg, g_Xg);
  cudaGetSymbolAddress(&pWB, g_WB);
  cudaGetSymbolAddress(&pAh, g_Ah);

  const int SMEM_MAIN = 4 * (128 * 80 + 256 * 80);  // 4 stages x 30720 = 122880
  const int SMEM_H    = 4 * (128 * 80 + 128 * 80);  // 4 stages x 20480 = 81920
  cudaFuncSetAttribute(mma_gemm_k<256,false>, cudaFuncAttributeMaxDynamicSharedMemorySize, SMEM_MAIN);
  cudaFuncSetAttribute(mma_gemm_k<128,true>,  cudaFuncAttributeMaxDynamicSharedMemorySize, SMEM_H);

  conv_pad_k   <<<(NTOK * 512) / 256, 256>>>(x, (__half*)pXg);  // x -> Xg[:, :4096]
  conv_pad_k   <<<(DOUT * 512) / 256, 256>>>(W, (__half*)pWB);  // W -> WB[:, :4096]
  conv_bstack_k<<<(NEXP * DOUT) / 256, 256>>>(B);               // B -> WB[:, 4096:]
  conv_flat_k  <<<(128 * DIN / 8) / 256, 256>>>(A);             // A -> Ah
  router_k     <<<NTOK / 8, 256>>>(x, Wr);                      // combine weights (x SCALING)

  // h-GEMM: g = (Xg[:, :4096] @ Ah^T) * comb -> f16 into Xg[:, 4096:4224]
  mma_gemm_k<128,true><<<dim3(1, NTOK/128), 256, SMEM_H>>>(
      (const __half*)pXg, KPAD, (const __half*)pAh, DIN, DIN/32, nullptr, nullptr);

  // main GEMM: Out = Xg @ WB^T + bias   (K = 4224 fuses base + lora)
  mma_gemm_k<256,false><<<dim3(DOUT/256, NTOK/128), 256, SMEM_MAIN>>>(
      (const __half*)pXg, KPAD, (const __half*)pWB, KPAD, KPAD/32, b, out);
}

// round 10
// speedup vs baseline: 1.2154x; 1.2154x over previous
#include <cuda_runtime.h>
#include <cuda_fp16.h>
#include <cstdint>

#define DIN   4096
#define DOUT  4096
#define NTOK  8192
#define KPAD  4224   /* DIN + 128 lora cols */
#define NEXP  8

// ---------------- scratch (device globals; no allocation) ----------------
__device__ __align__(1024) __half g_Xg[(size_t)NTOK * KPAD];    // [token,k] 0:4096 = x f16, 4096: = g
__device__ __align__(1024) __half g_WB[(size_t)DOUT * KPAD];    // [o,k]     0:4096 = W,    4096: = Bflat
__device__ __align__(1024) __half g_Ah[(size_t)128 * DIN];      // [e*16+r, k]
__device__ __align__(1024) float  g_hacc[4][(size_t)NTOK*128];  // split-K partial h
__device__ __align__(256)  float  g_comb[(size_t)NTOK * NEXP];  // scaled combine weights

// ---------------- helpers ----------------
__device__ __forceinline__ uint32_t smem_u32(const void* p){
  uint32_t a; asm("{ .reg .u64 t; cvta.to.shared.u64 t, %1; cvt.u32.u64 %0, t; }" : "=r"(a) : "l"(p)); return a;
}
__device__ __forceinline__ uint32_t ph2(float a, float b){
  __half2 h = __floats2half2_rn(a, b);
  return *reinterpret_cast<uint32_t*>(&h);
}
__device__ __forceinline__ void cp16(uint32_t saddr, const void* g){
  asm volatile("cp.async.cg.shared.global [%0], [%1], 16;" :: "r"(saddr), "l"(g));
}
__device__ __forceinline__ void ldm_x4(uint32_t* d, uint32_t addr){
  asm volatile("ldmatrix.sync.aligned.m8n8.x4.shared.b16 {%0,%1,%2,%3}, [%4];"
    : "=r"(d[0]), "=r"(d[1]), "=r"(d[2]), "=r"(d[3]) : "r"(addr));
}
__device__ __forceinline__ void mma16816(float* c, const uint32_t* a, const uint32_t* b){
  asm volatile("mma.sync.aligned.m16n8k16.row.col.f32.f16.f16.f32 "
    "{%0,%1,%2,%3}, {%4,%5,%6,%7}, {%8,%9}, {%0,%1,%2,%3};"
    : "+f"(c[0]), "+f"(c[1]), "+f"(c[2]), "+f"(c[3])
    : "r"(a[0]), "r"(a[1]), "r"(a[2]), "r"(a[3]), "r"(b[0]), "r"(b[1]));
}

// ---------------- x conversion: [8192,4096] fp32 -> Xg[:, :4096] f16 ----------------
__global__ void conv_x_k(const float* __restrict__ src){
  int gid = blockIdx.x * 256 + threadIdx.x;
  int row = gid >> 9, cb = gid & 511;
  const float4* s = reinterpret_cast<const float4*>(src + ((size_t)row << 12)) + (cb << 1);
  float4 a = s[0], b = s[1];
  uint4 o; o.x = ph2(a.x,a.y); o.y = ph2(a.z,a.w); o.z = ph2(b.x,b.y); o.w = ph2(b.z,b.w);
  *(reinterpret_cast<uint4*>(g_Xg + (size_t)row * KPAD) + cb) = o;
}

// ---------------- fused weight prep: W -> WB[:, :4096]; B_stack -> WB[:, 4096:]; A -> Ah ----
__global__ void prep_w_k(const float* __restrict__ W, const float* __restrict__ Bst,
                         const float* __restrict__ A){
  int bx = blockIdx.x;
  if (bx < 8192) {                                     // W conv (DOUT*512 8-elem groups)
    int gid = bx * 256 + threadIdx.x;
    int row = gid >> 9, cb = gid & 511;
    const float4* s = reinterpret_cast<const float4*>(W + ((size_t)row << 12)) + (cb << 1);
    float4 a = s[0], b = s[1];
    uint4 o; o.x = ph2(a.x,a.y); o.y = ph2(a.z,a.w); o.z = ph2(b.x,b.y); o.w = ph2(b.z,b.w);
    *(reinterpret_cast<uint4*>(g_WB + (size_t)row * KPAD) + cb) = o;
  } else if (bx < 8320) {                              // B_stack [8,4096,16] -> WB cols 4096+
    int gid = (bx - 8192) * 256 + threadIdx.x;         // 32768 threads: (e,o)
    int e = gid >> 12, o = gid & 4095;
    const float4* s = reinterpret_cast<const float4*>(Bst + (((size_t)(e << 12) + o) << 4));
    float4 a = s[0], b = s[1], c = s[2], d = s[3];
    uint4 o0; o0.x = ph2(a.x,a.y); o0.y = ph2(a.z,a.w); o0.z = ph2(b.x,b.y); o0.w = ph2(b.z,b.w);
    uint4 o1; o1.x = ph2(c.x,c.y); o1.y = ph2(c.z,c.w); o1.z = ph2(d.x,d.y); o1.w = ph2(d.z,d.w);
    uint4* dp = reinterpret_cast<uint4*>(g_WB + (size_t)o * KPAD + DIN + e * 16);
    dp[0] = o0; dp[1] = o1;
  } else {                                             // A_stack flat -> Ah (65536 groups)
    int gid = (bx - 8320) * 256 + threadIdx.x;
    const float4* s = reinterpret_cast<const float4*>(A) + (gid << 1);
    float4 a = s[0], b = s[1];
    uint4 o; o.x = ph2(a.x,a.y); o.y = ph2(a.z,a.w); o.z = ph2(b.x,b.y); o.w = ph2(b.z,b.w);
    *(reinterpret_cast<uint4*>(g_Ah) + gid) = o;
  }
}

// ---------------- router: exact fp32 top-2 softmax-renorm, SCALING folded ----------------
__global__ __launch_bounds__(256) void router_k(const float* __restrict__ x,
                                                const float* __restrict__ Wr){
  int t = blockIdx.x * 8 + (threadIdx.x >> 5);
  int lane = threadIdx.x & 31;
  const float4* xr = reinterpret_cast<const float4*>(x + ((size_t)t << 12));
  float acc[NEXP];
  #pragma unroll
  for (int e = 0; e < NEXP; ++e) acc[e] = 0.f;
  for (int i = 0; i < 32; ++i) {
    float4 xa = xr[lane + i * 32];
    #pragma unroll
    for (int e = 0; e < NEXP; ++e) {
      float4 w = reinterpret_cast<const float4*>(Wr + ((size_t)e << 12))[lane + i * 32];
      acc[e] += xa.x * w.x + xa.y * w.y + xa.z * w.z + xa.w * w.w;
    }
  }
  #pragma unroll
  for (int e = 0; e < NEXP; ++e)
    #pragma unroll
    for (int s = 16; s > 0; s >>= 1) acc[e] += __shfl_xor_sync(0xFFFFFFFFu, acc[e], s);
  if (lane == 0) {
    int i1 = 0; float m1 = acc[0];
    #pragma unroll
    for (int e = 1; e < NEXP; ++e) if (acc[e] > m1) { m1 = acc[e]; i1 = e; }
    int i2 = (i1 == 0) ? 1 : 0; float m2 = acc[i2];
    #pragma unroll
    for (int e = 0; e < NEXP; ++e) if (e != i1 && acc[e] > m2) { m2 = acc[e]; i2 = e; }
    float r  = expf(m2 - m1);
    float w1 = 1.f / (1.f + r);
    float w2 = r * w1;
    float o[NEXP];
    #pragma unroll
    for (int e = 0; e < NEXP; ++e) o[e] = 0.f;
    o[i1] = 2.0f * w1;  // SCALING = 32/16 = 2
    o[i2] = 2.0f * w2;
    #pragma unroll
    for (int e = 0; e < NEXP; ++e) g_comb[(size_t)t * NEXP + e] = o[e];
  }
}

// ---------------- mma.sync GEMM: C[128,128 tile] = A * B^T ----------------
// 256 thr, 8 warps as 4(m) x 2(n): warp tile 32x64. BK=32, 4-stage cp.async, single sync/chunk.
// Smem rows padded to 80B (conflict-free ldmatrix). 80KB smem -> 2 CTAs/SM.
// MODE 0: main GEMM, out = acc + bias[n] (fp32, ld DOUT). grid(x=nTile, y=mTile).
// MODE 1: h split-K, grid(x=kslice(4), y=mTile), nBase=0, out slice = g_hacc[kslice] (ld 128).
template<int MODE>
__global__ __launch_bounds__(256, 2)
void mma_gemm_k(const __half* __restrict__ Ag, int lda,
                const __half* __restrict__ Bg, int ldb, int nch,
                const float* __restrict__ bias, float* __restrict__ out){
  constexpr int NST = 4;
  constexpr int SSTA = 128 * 80;
  constexpr int SST  = SSTA + 128 * 80;      // 20480 B per stage
  extern __shared__ __align__(128) char smem[];
  const uint32_t sb = smem_u32(smem);

  const int tid = threadIdx.x, wid = tid >> 5, lane = tid & 31;
  const int wm = wid >> 1, wn = wid & 1;
  const int mBase = blockIdx.y * 128;
  const int nBase = (MODE == 0) ? blockIdx.x * 128 : 0;
  const int kc0   = (MODE == 0) ? 0 : blockIdx.x * nch;
  float* outp = (MODE == 0) ? out : out + (size_t)blockIdx.x * NTOK * 128;
  const int ldo = (MODE == 0) ? DOUT : 128;

  const uint32_t aOff = (uint32_t)(wm * 32 + (lane & 15)) * 80 + ((lane >> 4) * 16);
  const uint32_t bOff = (uint32_t)(wn * 64 + ((lane >> 4) & 1) * 8 + (lane & 7)) * 80
                        + (((lane >> 3) & 1) * 16);

  float acc[2][8][4];
  #pragma unroll
  for (int mt = 0; mt < 2; ++mt)
    #pragma unroll
    for (int nt = 0; nt < 8; ++nt)
      #pragma unroll
      for (int q = 0; q < 4; ++q) acc[mt][nt][q] = 0.f;

  auto load_stage = [&](int kc, int st){
    uint32_t sA = sb + st * SST;
    uint32_t sBs = sA + SSTA;
    const int kb = (kc0 + kc) * 32;
    #pragma unroll
    for (int i = 0; i < 2; ++i) {
      int s = tid + i * 256; int row = s >> 2, c = s & 3;
      cp16(sA + row * 80 + c * 16, Ag + (size_t)(mBase + row) * lda + kb + c * 8);
    }
    #pragma unroll
    for (int i = 0; i < 2; ++i) {
      int s = tid + i * 256; int row = s >> 2, c = s & 3;
      cp16(sBs + row * 80 + c * 16, Bg + (size_t)(nBase + row) * ldb + kb + c * 8);
    }
    asm volatile("cp.async.commit_group;" ::: "memory");
  };

  #pragma unroll
  for (int s = 0; s < NST - 1; ++s) load_stage(s, s);

  #pragma unroll 1
  for (int kc = 0; kc < nch; ++kc) {
    asm volatile("cp.async.wait_group %0;" :: "n"(NST - 2) : "memory");
    __syncthreads();                       // single sync: stage kc ready; slot (kc-1)&3 free
    const int wst = kc + NST - 1;
    if (wst < nch) load_stage(wst, wst & (NST - 1));

    const int st = kc & (NST - 1);
    const uint32_t sA = sb + st * SST + aOff;
    const uint32_t sB = sb + st * SST + SSTA + bOff;
    #pragma unroll
    for (int kk = 0; kk < 2; ++kk) {
      uint32_t a[2][4];
      #pragma unroll
      for (int mt = 0; mt < 2; ++mt) ldm_x4(a[mt], sA + mt * (16 * 80) + kk * 32);
      uint32_t b[8][2];
      #pragma unroll
      for (int bp = 0; bp < 4; ++bp) {
        uint32_t d[4];
        ldm_x4(d, sB + bp * (16 * 80) + kk * 32);
        b[2*bp][0] = d[0]; b[2*bp][1] = d[1];
        b[2*bp+1][0] = d[2]; b[2*bp+1][1] = d[3];
      }
      #pragma unroll
      for (int mt = 0; mt < 2; ++mt)
        #pragma unroll
        for (int nt = 0; nt < 8; ++nt)
          mma16816(acc[mt][nt], a[mt], b[nt]);
    }
  }

  // epilogue
  const int m0 = mBase + wm * 32 + (lane >> 2);
  const int n0 = nBase + wn * 64 + (lane & 3) * 2;
  #pragma unroll
  for (int mt = 0; mt < 2; ++mt) {
    const int r0 = m0 + mt * 16, r1 = r0 + 8;
    #pragma unroll
    for (int nt = 0; nt < 8; ++nt) {
      const int n = n0 + nt * 8;
      if (MODE == 0) {
        const float2 bv = *reinterpret_cast<const float2*>(bias + n);
        float2 v0; v0.x = acc[mt][nt][0] + bv.x; v0.y = acc[mt][nt][1] + bv.y;
        float2 v1; v1.x = acc[mt][nt][2] + bv.x; v1.y = acc[mt][nt][3] + bv.y;
        *reinterpret_cast<float2*>(outp + (size_t)r0 * ldo + n) = v0;
        *reinterpret_cast<float2*>(outp + (size_t)r1 * ldo + n) = v1;
      } else {
        float2 v0; v0.x = acc[mt][nt][0]; v0.y = acc[mt][nt][1];
        float2 v1; v1.x = acc[mt][nt][2]; v1.y = acc[mt][nt][3];
        *reinterpret_cast<float2*>(outp + (size_t)r0 * ldo + n) = v0;
        *reinterpret_cast<float2*>(outp + (size_t)r1 * ldo + n) = v1;
      }
    }
  }
}

// ---------------- h epilogue: sum 4 slices, scale by comb, f16 into Xg[:, 4096:] ----------
__global__ void h_epi_k(){
  int gid = blockIdx.x * 256 + threadIdx.x;   // 262144 = 8192 rows x 32 col-groups
  int m = gid >> 5, c4 = gid & 31;
  int n = c4 * 4;
  const size_t off = (size_t)m * 128 + n;
  float4 s0 = *reinterpret_cast<const float4*>(&g_hacc[0][off]);
  float4 s1 = *reinterpret_cast<const float4*>(&g_hacc[1][off]);
  float4 s2 = *reinterpret_cast<const float4*>(&g_hacc[2][off]);
  float4 s3 = *reinterpret_cast<const float4*>(&g_hacc[3][off]);
  float sc = g_comb[(size_t)m * NEXP + (n >> 4)];
  float a = (s0.x + s1.x + s2.x + s3.x) * sc;
  float b = (s0.y + s1.y + s2.y + s3.y) * sc;
  float c = (s0.z + s1.z + s2.z + s3.z) * sc;
  float d = (s0.w + s1.w + s2.w + s3.w) * sc;
  uint2 o; o.x = ph2(a, b); o.y = ph2(c, d);
  *reinterpret_cast<uint2*>(g_Xg + (size_t)m * KPAD + DIN + n) = o;
}

// ---------------- host ----------------
extern "C" void kernel_launch(void* const* d_in, const int* in_sizes, int n_in,
                              void* d_out, int out_size){
  (void)in_sizes; (void)n_in; (void)out_size;
  const float* x   = (const float*)d_in[0];
  const float* W   = (const float*)d_in[1];
  const float* b   = (const float*)d_in[2];
  const float* Wr  = (const float*)d_in[3];
  const float* A   = (const float*)d_in[4];
  const float* B   = (const float*)d_in[5];
  float* out = (float*)d_out;

  void *pXg = nullptr, *pWB = nullptr, *pAh = nullptr, *pHacc = nullptr;
  cudaGetSymbolAddress(&pXg, g_Xg);
  cudaGetSymbolAddress(&pWB, g_WB);
  cudaGetSymbolAddress(&pAh, g_Ah);
  cudaGetSymbolAddress(&pHacc, g_hacc);

  const int SMEM = 4 * (128 * 80 + 128 * 80);  // 81920
  cudaFuncSetAttribute(mma_gemm_k<0>, cudaFuncAttributeMaxDynamicSharedMemorySize, SMEM);
  cudaFuncSetAttribute(mma_gemm_k<1>, cudaFuncAttributeMaxDynamicSharedMemorySize, SMEM);

  // 1: weights prep (W, B_stack, A_stack -> f16 scratch)
  prep_w_k<<<8576, 256>>>(W, B, A);
  // 2: x -> f16
  conv_x_k<<<(NTOK * 512) / 256, 256>>>(x);
  // 3: router
  router_k<<<NTOK / 8, 256>>>(x, Wr);
  // 4: h split-K GEMM: g_hacc[s] = Xg[:, s*1024:(s+1)*1024] @ Ah[:, s*1024:...]^T
  mma_gemm_k<1><<<dim3(4, NTOK/128), 256, SMEM>>>(
      (const __half*)pXg, KPAD, (const __half*)pAh, DIN, 32, nullptr, (float*)pHacc);
  // 5: reduce slices, scale by comb, write f16 lora activations into Xg[:, 4096:]
  h_epi_k<<<(NTOK * 32) / 256, 256>>>();
  // 6: main GEMM: Out = Xg @ WB^T + bias (K = 4224 fuses base + lora)
  mma_gemm_k<0><<<dim3(DOUT/128, NTOK/128), 256, SMEM>>>(
      (const __half*)pXg, KPAD, (const __half*)pWB, KPAD, KPAD/32, b, out);
}

// round 14
// speedup vs baseline: 1.3211x; 1.0870x over previous
#include <cuda_runtime.h>
#include <cuda_fp16.h>
#include <cstdint>

#define DIN   4096
#define DOUT  4096
#define NTOK  8192
#define KPAD  4224   /* DIN + 128 lora cols */
#define NEXP  8

// ---------------- scratch (device globals; no allocation) ----------------
__device__ __align__(1024) __half g_Xg[(size_t)NTOK * KPAD];    // [token,k] 0:4096 = x f16, 4096: = g
__device__ __align__(1024) __half g_WB[(size_t)DOUT * KPAD];    // [o,k]     0:4096 = W,    4096: = Bflat
__device__ __align__(1024) __half g_Ah[(size_t)128 * DIN];      // [e*16+r, k]
__device__ __align__(1024) float  g_hacc[4][(size_t)NTOK*128];  // split-K partial h
__device__ __align__(256)  float  g_comb[(size_t)NTOK * NEXP];  // scaled combine weights

// ---------------- helpers ----------------
__device__ __forceinline__ uint32_t smem_u32(const void* p){
  uint32_t a; asm("{ .reg .u64 t; cvta.to.shared.u64 t, %1; cvt.u32.u64 %0, t; }" : "=r"(a) : "l"(p)); return a;
}
__device__ __forceinline__ uint32_t ph2(float a, float b){
  __half2 h = __floats2half2_rn(a, b);
  return *reinterpret_cast<uint32_t*>(&h);
}
__device__ __forceinline__ void cp16(uint32_t saddr, const void* g){
  asm volatile("cp.async.cg.shared.global [%0], [%1], 16;" :: "r"(saddr), "l"(g));
}
__device__ __forceinline__ void ldm_x4(uint32_t* d, uint32_t addr){
  asm volatile("ldmatrix.sync.aligned.m8n8.x4.shared.b16 {%0,%1,%2,%3}, [%4];"
    : "=r"(d[0]), "=r"(d[1]), "=r"(d[2]), "=r"(d[3]) : "r"(addr));
}
__device__ __forceinline__ void mma16816(float* c, const uint32_t* a, const uint32_t* b){
  asm volatile("mma.sync.aligned.m16n8k16.row.col.f32.f16.f16.f32 "
    "{%0,%1,%2,%3}, {%4,%5,%6,%7}, {%8,%9}, {%0,%1,%2,%3};"
    : "+f"(c[0]), "+f"(c[1]), "+f"(c[2]), "+f"(c[3])
    : "r"(a[0]), "r"(a[1]), "r"(a[2]), "r"(a[3]), "r"(b[0]), "r"(b[1]));
}

// ---------------- x conversion: [8192,4096] fp32 -> Xg[:, :4096] f16 ----------------
__global__ void conv_x_k(const float* __restrict__ src){
  int gid = blockIdx.x * 256 + threadIdx.x;
  int row = gid >> 9, cb = gid & 511;
  const float4* s = reinterpret_cast<const float4*>(src + ((size_t)row << 12)) + (cb << 1);
  float4 a = s[0], b = s[1];
  uint4 o; o.x = ph2(a.x,a.y); o.y = ph2(a.z,a.w); o.z = ph2(b.x,b.y); o.w = ph2(b.z,b.w);
  *(reinterpret_cast<uint4*>(g_Xg + (size_t)row * KPAD) + cb) = o;
}

// ---------------- fused weight prep: W -> WB[:, :4096]; B_stack -> WB[:, 4096:]; A -> Ah ----
__global__ void prep_w_k(const float* __restrict__ W, const float* __restrict__ Bst,
                         const float* __restrict__ A){
  int bx = blockIdx.x;
  if (bx < 8192) {                                     // W conv (DOUT*512 8-elem groups)
    int gid = bx * 256 + threadIdx.x;
    int row = gid >> 9, cb = gid & 511;
    const float4* s = reinterpret_cast<const float4*>(W + ((size_t)row << 12)) + (cb << 1);
    float4 a = s[0], b = s[1];
    uint4 o; o.x = ph2(a.x,a.y); o.y = ph2(a.z,a.w); o.z = ph2(b.x,b.y); o.w = ph2(b.z,b.w);
    *(reinterpret_cast<uint4*>(g_WB + (size_t)row * KPAD) + cb) = o;
  } else if (bx < 8320) {                              // B_stack [8,4096,16] -> WB cols 4096+
    int gid = (bx - 8192) * 256 + threadIdx.x;         // 32768 threads: (e,o)
    int e = gid >> 12, o = gid & 4095;
    const float4* s = reinterpret_cast<const float4*>(Bst + (((size_t)(e << 12) + o) << 4));
    float4 a = s[0], b = s[1], c = s[2], d = s[3];
    uint4 o0; o0.x = ph2(a.x,a.y); o0.y = ph2(a.z,a.w); o0.z = ph2(b.x,b.y); o0.w = ph2(b.z,b.w);
    uint4 o1; o1.x = ph2(c.x,c.y); o1.y = ph2(c.z,c.w); o1.z = ph2(d.x,d.y); o1.w = ph2(d.z,d.w);
    uint4* dp = reinterpret_cast<uint4*>(g_WB + (size_t)o * KPAD + DIN + e * 16);
    dp[0] = o0; dp[1] = o1;
  } else {                                             // A_stack flat -> Ah (65536 groups)
    int gid = (bx - 8320) * 256 + threadIdx.x;
    const float4* s = reinterpret_cast<const float4*>(A) + (gid << 1);
    float4 a = s[0], b = s[1];
    uint4 o; o.x = ph2(a.x,a.y); o.y = ph2(a.z,a.w); o.z = ph2(b.x,b.y); o.w = ph2(b.z,b.w);
    *(reinterpret_cast<uint4*>(g_Ah) + gid) = o;
  }
}

// ---------------- router: exact fp32 top-2 softmax-renorm, SCALING folded ----------------
__global__ __launch_bounds__(256) void router_k(const float* __restrict__ x,
                                                const float* __restrict__ Wr){
  int t = blockIdx.x * 8 + (threadIdx.x >> 5);
  int lane = threadIdx.x & 31;
  const float4* xr = reinterpret_cast<const float4*>(x + ((size_t)t << 12));
  float acc[NEXP];
  #pragma unroll
  for (int e = 0; e < NEXP; ++e) acc[e] = 0.f;
  for (int i = 0; i < 32; ++i) {
    float4 xa = xr[lane + i * 32];
    #pragma unroll
    for (int e = 0; e < NEXP; ++e) {
      float4 w = reinterpret_cast<const float4*>(Wr + ((size_t)e << 12))[lane + i * 32];
      acc[e] += xa.x * w.x + xa.y * w.y + xa.z * w.z + xa.w * w.w;
    }
  }
  #pragma unroll
  for (int e = 0; e < NEXP; ++e)
    #pragma unroll
    for (int s = 16; s > 0; s >>= 1) acc[e] += __shfl_xor_sync(0xFFFFFFFFu, acc[e], s);
  if (lane == 0) {
    int i1 = 0; float m1 = acc[0];
    #pragma unroll
    for (int e = 1; e < NEXP; ++e) if (acc[e] > m1) { m1 = acc[e]; i1 = e; }
    int i2 = (i1 == 0) ? 1 : 0; float m2 = acc[i2];
    #pragma unroll
    for (int e = 0; e < NEXP; ++e) if (e != i1 && acc[e] > m2) { m2 = acc[e]; i2 = e; }
    float r  = expf(m2 - m1);
    float w1 = 1.f / (1.f + r);
    float w2 = r * w1;
    float o[NEXP];
    #pragma unroll
    for (int e = 0; e < NEXP; ++e) o[e] = 0.f;
    o[i1] = 2.0f * w1;  // SCALING = 32/16 = 2
    o[i2] = 2.0f * w2;
    #pragma unroll
    for (int e = 0; e < NEXP; ++e) g_comb[(size_t)t * NEXP + e] = o[e];
  }
}

// ---------------- mma.sync GEMM: C[128,128 tile] = A * B^T ----------------
// 256 thr, 8 warps as 4(m) x 2(n): warp tile 32x64. BK=64, NST=3, single sync/chunk.
// Rows padded to 144B (conflict-free ldmatrix: bank step 36%32=4). 108KB smem -> 2 CTAs/SM.
// Fragments double-buffered over kk: prefetch kk+1's ldmatrix during kk's mma burst.
// MODE 0: main GEMM, out = acc + bias[n]. grid(x=nTile, y=mTile).
// MODE 1: h split-K, grid(x=kslice(4), y=mTile), out slice = g_hacc[kslice].
template<int MODE>
__global__ __launch_bounds__(256, 2)
void mma_gemm_k(const __half* __restrict__ Ag, int lda,
                const __half* __restrict__ Bg, int ldb, int nch,
                const float* __restrict__ bias, float* __restrict__ out){
  constexpr int NST = 3;
  constexpr int ROWB = 144;                  // 128B data + 16B pad
  constexpr int SSTA = 128 * ROWB;           // 18432
  constexpr int SST  = 2 * SSTA;             // 36864 per stage
  extern __shared__ __align__(128) char smem[];
  const uint32_t sb = smem_u32(smem);

  const int tid = threadIdx.x, wid = tid >> 5, lane = tid & 31;
  const int wm = wid >> 1, wn = wid & 1;
  const int mBase = blockIdx.y * 128;
  const int nBase = (MODE == 0) ? blockIdx.x * 128 : 0;
  const int kc0   = (MODE == 0) ? 0 : blockIdx.x * nch;
  float* outp = (MODE == 0) ? out : out + (size_t)blockIdx.x * NTOK * 128;
  const int ldo = (MODE == 0) ? DOUT : 128;

  const uint32_t aOff = (uint32_t)(wm * 32 + (lane & 15)) * ROWB + ((lane >> 4) * 16);
  const uint32_t bOff = (uint32_t)(wn * 64 + ((lane >> 4) & 1) * 8 + (lane & 7)) * ROWB
                        + (((lane >> 3) & 1) * 16);

  float acc[2][8][4];
  #pragma unroll
  for (int mt = 0; mt < 2; ++mt)
    #pragma unroll
    for (int nt = 0; nt < 8; ++nt)
      #pragma unroll
      for (int q = 0; q < 4; ++q) acc[mt][nt][q] = 0.f;

  auto load_stage = [&](int kc, int st){
    uint32_t sA = sb + st * SST;
    uint32_t sBs = sA + SSTA;
    const int kb = (kc0 + kc) * 64;
    #pragma unroll
    for (int i = 0; i < 4; ++i) {            // A: 1024 16B segs
      int s = tid + i * 256; int row = s >> 3, c = s & 7;
      cp16(sA + row * ROWB + c * 16, Ag + (size_t)(mBase + row) * lda + kb + c * 8);
    }
    #pragma unroll
    for (int i = 0; i < 4; ++i) {            // B: 1024 16B segs
      int s = tid + i * 256; int row = s >> 3, c = s & 7;
      cp16(sBs + row * ROWB + c * 16, Bg + (size_t)(nBase + row) * ldb + kb + c * 8);
    }
    asm volatile("cp.async.commit_group;" ::: "memory");
  };

  load_stage(0, 0);
  load_stage(1, 1);

  uint32_t afr[2][2][4];
  uint32_t bfr[2][8][2];

  int st = 0, wstSlot = 2;
  #pragma unroll 1
  for (int kc = 0; kc < nch; ++kc) {
    asm volatile("cp.async.wait_group %0;" :: "n"(NST - 2) : "memory");
    __syncthreads();                         // stage kc ready; slot (kc-1)%3 free
    if (kc + 2 < nch) load_stage(kc + 2, wstSlot);

    const uint32_t sA = sb + st * SST + aOff;
    const uint32_t sB = sb + st * SST + SSTA + bOff;

    // kk fragment loader (kk in 0..3, 16B col step 32B per kk)
    auto ldfrag = [&](int kk, int pb){
      #pragma unroll
      for (int mt = 0; mt < 2; ++mt)
        ldm_x4(afr[pb][mt], sA + mt * (16 * ROWB) + kk * 32);
      #pragma unroll
      for (int bp = 0; bp < 4; ++bp) {
        uint32_t d[4];
        ldm_x4(d, sB + bp * (16 * ROWB) + kk * 32);
        bfr[pb][2*bp][0] = d[0]; bfr[pb][2*bp][1] = d[1];
        bfr[pb][2*bp+1][0] = d[2]; bfr[pb][2*bp+1][1] = d[3];
      }
    };

    ldfrag(0, 0);
    #pragma unroll
    for (int kk = 0; kk < 4; ++kk) {
      if (kk < 3) ldfrag(kk + 1, (kk + 1) & 1);
      const int pb = kk & 1;
      #pragma unroll
      for (int mt = 0; mt < 2; ++mt)
        #pragma unroll
        for (int nt = 0; nt < 8; ++nt)
          mma16816(acc[mt][nt], afr[pb][mt], bfr[pb][nt]);
    }

    if (++st == NST) st = 0;
    if (++wstSlot == NST) wstSlot = 0;
  }

  // epilogue
  const int m0 = mBase + wm * 32 + (lane >> 2);
  const int n0 = nBase + wn * 64 + (lane & 3) * 2;
  #pragma unroll
  for (int mt = 0; mt < 2; ++mt) {
    const int r0 = m0 + mt * 16, r1 = r0 + 8;
    #pragma unroll
    for (int nt = 0; nt < 8; ++nt) {
      const int n = n0 + nt * 8;
      if (MODE == 0) {
        const float2 bv = *reinterpret_cast<const float2*>(bias + n);
        float2 v0; v0.x = acc[mt][nt][0] + bv.x; v0.y = acc[mt][nt][1] + bv.y;
        float2 v1; v1.x = acc[mt][nt][2] + bv.x; v1.y = acc[mt][nt][3] + bv.y;
        *reinterpret_cast<float2*>(outp + (size_t)r0 * ldo + n) = v0;
        *reinterpret_cast<float2*>(outp + (size_t)r1 * ldo + n) = v1;
      } else {
        float2 v0; v0.x = acc[mt][nt][0]; v0.y = acc[mt][nt][1];
        float2 v1; v1.x = acc[mt][nt][2]; v1.y = acc[mt][nt][3];
        *reinterpret_cast<float2*>(outp + (size_t)r0 * ldo + n) = v0;
        *reinterpret_cast<float2*>(outp + (size_t)r1 * ldo + n) = v1;
      }
    }
  }
}

// ---------------- h epilogue: sum 4 slices, scale by comb, f16 into Xg[:, 4096:] ----------
__global__ void h_epi_k(){
  int gid = blockIdx.x * 256 + threadIdx.x;   // 262144 = 8192 rows x 32 col-groups
  int m = gid >> 5, c4 = gid & 31;
  int n = c4 * 4;
  const size_t off = (size_t)m * 128 + n;
  float4 s0 = *reinterpret_cast<const float4*>(&g_hacc[0][off]);
  float4 s1 = *reinterpret_cast<const float4*>(&g_hacc[1][off]);
  float4 s2 = *reinterpret_cast<const float4*>(&g_hacc[2][off]);
  float4 s3 = *reinterpret_cast<const float4*>(&g_hacc[3][off]);
  float sc = g_comb[(size_t)m * NEXP + (n >> 4)];
  float a = (s0.x + s1.x + s2.x + s3.x) * sc;
  float b = (s0.y + s1.y + s2.y + s3.y) * sc;
  float c = (s0.z + s1.z + s2.z + s3.z) * sc;
  float d = (s0.w + s1.w + s2.w + s3.w) * sc;
  uint2 o; o.x = ph2(a, b); o.y = ph2(c, d);
  *reinterpret_cast<uint2*>(g_Xg + (size_t)m * KPAD + DIN + n) = o;
}

// ---------------- host ----------------
extern "C" void kernel_launch(void* const* d_in, const int* in_sizes, int n_in,
                              void* d_out, int out_size){
  (void)in_sizes; (void)n_in; (void)out_size;
  const float* x   = (const float*)d_in[0];
  const float* W   = (const float*)d_in[1];
  const float* b   = (const float*)d_in[2];
  const float* Wr  = (const float*)d_in[3];
  const float* A   = (const float*)d_in[4];
  const float* B   = (const float*)d_in[5];
  float* out = (float*)d_out;

  void *pXg = nullptr, *pWB = nullptr, *pAh = nullptr, *pHacc = nullptr;
  cudaGetSymbolAddress(&pXg, g_Xg);
  cudaGetSymbolAddress(&pWB, g_WB);
  cudaGetSymbolAddress(&pAh, g_Ah);
  cudaGetSymbolAddress(&pHacc, g_hacc);

  const int SMEM = 3 * 2 * 128 * 144;   // 110592 per CTA -> 2 CTAs/SM (221184 <= 228KB)
  cudaFuncSetAttribute(mma_gemm_k<0>, cudaFuncAttributeMaxDynamicSharedMemorySize, SMEM);
  cudaFuncSetAttribute(mma_gemm_k<1>, cudaFuncAttributeMaxDynamicSharedMemorySize, SMEM);

  // 1: weights prep (W, B_stack, A_stack -> f16 scratch)
  prep_w_k<<<8576, 256>>>(W, B, A);
  // 2: x -> f16
  conv_x_k<<<(NTOK * 512) / 256, 256>>>(x);
  // 3: router
  router_k<<<NTOK / 8, 256>>>(x, Wr);
  // 4: h split-K GEMM: g_hacc[s] = Xg[:, s*1024:(s+1)*1024] @ Ah[:, s*1024:...]^T (16 chunks of 64)
  mma_gemm_k<1><<<dim3(4, NTOK/128), 256, SMEM>>>(
      (const __half*)pXg, KPAD, (const __half*)pAh, DIN, 16, nullptr, (float*)pHacc);
  // 5: reduce slices, scale by comb, write f16 lora activations into Xg[:, 4096:]
  h_epi_k<<<(NTOK * 32) / 256, 256>>>();
  // 6: main GEMM: Out = Xg @ WB^T + bias (K = 4224 fuses base + lora, 66 chunks of 64)
  mma_gemm_k<0><<<dim3(DOUT/128, NTOK/128), 256, SMEM>>>(
      (const __half*)pXg, KPAD, (const __half*)pWB, KPAD, KPAD/64, b, out);
}